// round 4
// baseline (speedup 1.0000x reference)
#include <cuda_runtime.h>

// Problem constants (fixed shapes from reference)
#define BT_   4096   // B*T
#define L_    16
#define E_    256
#define H_    512
#define G4_   2048   // 4*H
#define VOC_  256

// Scratch in __device__ globals (no allocation allowed in kernel_launch)
__device__ float g_XG[VOC_ * G4_];     // 2 MB  : per-vocab input-gate precompute (+bias)
__device__ float g_gates[BT_ * G4_];   // 32 MB : per-step gate pre-activations
__device__ float g_c[BT_ * H_];        // 8 MB  : cell state

// ---------------------------------------------------------------------------
// Zero h (lives in d_out) and c
// ---------------------------------------------------------------------------
__global__ void init_kernel(float* __restrict__ h) {
    int i = blockIdx.x * blockDim.x + threadIdx.x;
    if (i < BT_ * H_) {
        h[i] = 0.f;
        g_c[i] = 0.f;
    }
}

// ---------------------------------------------------------------------------
// XG[v][n] = sum_e emb[v][e] * W_ih[n][e] + b_ih[n] + b_hh[n]
// 256 x 2048 x 256 GEMM — tiny one-time cost, simple 16x16 tiles.
// ---------------------------------------------------------------------------
__global__ void xg_kernel(const float* __restrict__ emb,
                          const float* __restrict__ W_ih,
                          const float* __restrict__ b_ih,
                          const float* __restrict__ b_hh) {
    __shared__ float Es[16][16];
    __shared__ float Ws[16][17];
    int tx = threadIdx.x, ty = threadIdx.y;
    int n = blockIdx.x * 16 + tx;
    int v = blockIdx.y * 16 + ty;
    float acc = 0.f;
    for (int k0 = 0; k0 < E_; k0 += 16) {
        Es[ty][tx] = emb[v * E_ + k0 + tx];
        Ws[ty][tx] = W_ih[(blockIdx.x * 16 + ty) * E_ + k0 + tx];
        __syncthreads();
#pragma unroll
        for (int k = 0; k < 16; k++) acc += Es[ty][k] * Ws[tx][k];
        __syncthreads();
    }
    g_XG[v * G4_ + n] = acc + b_ih[n] + b_hh[n];
}

// ---------------------------------------------------------------------------
// Recurrent GEMM: gates[m][n] = sum_k h[m][k] * W_hh[n][k] + XG[seq[m][t]][n]
// M=4096, N=2048, K=512. 128x128 block tile, BK=8, 256 threads, 8x8 microtile.
// Both A (h) and B (W_hh) are K-contiguous row-major -> coalesced float4 loads,
// transposed scatter into k-major smem tiles.
// ---------------------------------------------------------------------------
__global__ void __launch_bounds__(256)
gemm_kernel(const float* __restrict__ h,
            const float* __restrict__ W,
            const int* __restrict__ seq,
            int t) {
    __shared__ float As[8][128];
    __shared__ float Bs[8][128];

    const int tid  = threadIdx.x;
    const int bm   = blockIdx.y * 128;
    const int bn   = blockIdx.x * 128;
    const int lrow = tid >> 1;          // 0..127
    const int lk4  = (tid & 1) << 2;    // 0 or 4
    const float* Ap = h + (bm + lrow) * H_ + lk4;
    const float* Bp = W + (bn + lrow) * H_ + lk4;
    const int tx = tid & 15;            // N microtile: cols tx*8..tx*8+7
    const int ty = tid >> 4;            // M microtile: rows ty*8..ty*8+7

    float acc[8][8];
#pragma unroll
    for (int i = 0; i < 8; i++)
#pragma unroll
        for (int j = 0; j < 8; j++) acc[i][j] = 0.f;

    for (int k0 = 0; k0 < H_; k0 += 8) {
        float4 a = *(const float4*)(Ap + k0);
        float4 b = *(const float4*)(Bp + k0);
        As[lk4 + 0][lrow] = a.x; As[lk4 + 1][lrow] = a.y;
        As[lk4 + 2][lrow] = a.z; As[lk4 + 3][lrow] = a.w;
        Bs[lk4 + 0][lrow] = b.x; Bs[lk4 + 1][lrow] = b.y;
        Bs[lk4 + 2][lrow] = b.z; Bs[lk4 + 3][lrow] = b.w;
        __syncthreads();
#pragma unroll
        for (int k = 0; k < 8; k++) {
            float4 a0 = *(const float4*)&As[k][ty * 8];
            float4 a1 = *(const float4*)&As[k][ty * 8 + 4];
            float4 b0 = *(const float4*)&Bs[k][tx * 8];
            float4 b1 = *(const float4*)&Bs[k][tx * 8 + 4];
            float ar[8] = {a0.x, a0.y, a0.z, a0.w, a1.x, a1.y, a1.z, a1.w};
            float br[8] = {b0.x, b0.y, b0.z, b0.w, b1.x, b1.y, b1.z, b1.w};
#pragma unroll
            for (int i = 0; i < 8; i++)
#pragma unroll
                for (int j = 0; j < 8; j++)
                    acc[i][j] = fmaf(ar[i], br[j], acc[i][j]);
        }
        __syncthreads();
    }

    // Epilogue: add per-token input-projection row (XG lookup) and store gates.
#pragma unroll
    for (int i = 0; i < 8; i++) {
        int m  = bm + ty * 8 + i;
        int id = seq[m * L_ + t];  // char_seq_padded[m][t]
        const float4* xg = (const float4*)(g_XG + id * G4_ + bn + tx * 8);
        float4* gp = (float4*)(g_gates + m * G4_ + bn + tx * 8);
        float4 x0 = xg[0], x1 = xg[1];
        float4 o0 = make_float4(acc[i][0] + x0.x, acc[i][1] + x0.y,
                                acc[i][2] + x0.z, acc[i][3] + x0.w);
        float4 o1 = make_float4(acc[i][4] + x1.x, acc[i][5] + x1.y,
                                acc[i][6] + x1.z, acc[i][7] + x1.w);
        gp[0] = o0; gp[1] = o1;
    }
}

// ---------------------------------------------------------------------------
// LSTM cell pointwise + length mask (conditional update == mask blend)
// ---------------------------------------------------------------------------
__device__ __forceinline__ float sigmoidf_(float x) {
    return 1.f / (1.f + expf(-x));
}

__global__ void pointwise_kernel(const int* __restrict__ lens,
                                 float* __restrict__ h, int t) {
    int idx = blockIdx.x * blockDim.x + threadIdx.x;
    if (idx >= BT_ * H_) return;
    int m = idx >> 9;            // H_ = 512
    if (lens[m] <= t) return;    // past this sequence's length: keep h, c
    int j = idx & (H_ - 1);
    const float* gr = g_gates + m * G4_;
    float ig = sigmoidf_(gr[j]);
    float fg = sigmoidf_(gr[H_ + j]);
    float gg = tanhf(gr[2 * H_ + j]);
    float og = sigmoidf_(gr[3 * H_ + j]);
    float cn = fg * g_c[idx] + ig * gg;
    g_c[idx] = cn;
    h[idx] = og * tanhf(cn);
}

// ---------------------------------------------------------------------------
// Launch: init -> XG precompute -> 16 x (gemm, pointwise). Graph-capturable.
// ---------------------------------------------------------------------------
extern "C" void kernel_launch(void* const* d_in, const int* in_sizes, int n_in,
                              void* d_out, int out_size) {
    const int*   seq  = (const int*)d_in[0];     // [32,128,16] int32
    const int*   lens = (const int*)d_in[1];     // [32,128]    int32
    const float* emb  = (const float*)d_in[2];   // [256,256]
    const float* W_ih = (const float*)d_in[3];   // [2048,256]
    const float* W_hh = (const float*)d_in[4];   // [2048,512]
    const float* b_ih = (const float*)d_in[5];   // [2048]
    const float* b_hh = (const float*)d_in[6];   // [2048]
    float* h = (float*)d_out;                    // [4096,512] = final hidden state

    init_kernel<<<(BT_ * H_ + 255) / 256, 256>>>(h);

    dim3 xgrid(G4_ / 16, VOC_ / 16);
    xg_kernel<<<xgrid, dim3(16, 16)>>>(emb, W_ih, b_ih, b_hh);

    dim3 ggrid(G4_ / 128, BT_ / 128);   // (16, 32) = 512 CTAs
    for (int t = 0; t < L_; t++) {
        gemm_kernel<<<ggrid, 256>>>(h, W_hh, seq, t);
        pointwise_kernel<<<(BT_ * H_ + 255) / 256, 256>>>(lens, h, t);
    }
}